// round 13
// baseline (speedup 1.0000x reference)
#include <cuda_runtime.h>
#include <cuda_bf16.h>
#include <math.h>

#define BB   16
#define KK   32
#define HH   28
#define WW   28
#define HID  64
#define OUT  64
#define NIMG (BB*KK)          // 512

typedef unsigned long long u64;

// ---------------- scratch ----------------
__device__ float g_h1[NIMG * 32 * 14 * 14];
__device__ float g_h2[NIMG * 64 * 7 * 7];
__device__ float g_feat[NIMG * HID];
__device__ float g_part[NIMG * OUT];

// ---------------- packed fp32x2 helpers ----------------
__device__ __forceinline__ u64 pack2(float x, float y) {
    u64 r; asm("mov.b64 %0,{%1,%2};" : "=l"(r) : "f"(x), "f"(y)); return r;
}
__device__ __forceinline__ void unpack2(u64 p, float& x, float& y) {
    asm("mov.b64 {%0,%1},%2;" : "=f"(x), "=f"(y) : "l"(p));
}
__device__ __forceinline__ u64 ffma2(u64 a, u64 b, u64 c) {
    u64 d; asm("fma.rn.f32x2 %0,%1,%2,%3;" : "=l"(d) : "l"(a), "l"(b), "l"(c)); return d;
}

// =========================================================================
// Kernel 1: conv1 (1->32, 3x3 SAME) + relu + maxpool2
// =========================================================================
__global__ __launch_bounds__(256) void conv1_kernel(
    const float* __restrict__ x, const float* __restrict__ w,
    const float* __restrict__ bias)
{
    __shared__ float sin1[30 * 30];
    __shared__ float sw1[32 * 9];
    __shared__ float sb1[32];

    const int img = blockIdx.x;
    const int tid = threadIdx.x;

    for (int i = tid; i < 900; i += 256) sin1[i] = 0.f;
    for (int i = tid; i < 288; i += 256) sw1[i] = w[i];
    if (tid < 32) sb1[tid] = bias[tid];
    __syncthreads();
    for (int i = tid; i < 784; i += 256) {
        int y = i / 28, xx = i % 28;
        sin1[(y + 1) * 30 + xx + 1] = x[img * 784 + i];
    }
    __syncthreads();

    for (int item = tid; item < 32 * 196; item += 256) {
        int c = item / 196, p = item % 196;
        int oy = p / 14, ox = p % 14;
        const float* wp = sw1 + c * 9;
        const float bv = sb1[c];
        float m = 0.f;
        #pragma unroll
        for (int py = 0; py < 2; py++) {
            #pragma unroll
            for (int px = 0; px < 2; px++) {
                int r = 2 * oy + py, col = 2 * ox + px;
                float s = bv;
                #pragma unroll
                for (int ky = 0; ky < 3; ky++)
                    #pragma unroll
                    for (int kx = 0; kx < 3; kx++)
                        s += sin1[(r + ky) * 30 + col + kx] * wp[ky * 3 + kx];
                m = fmaxf(m, s);
            }
        }
        g_h1[img * (32 * 196) + item] = m;
    }
}

// =========================================================================
// Kernel 2: conv2 (32->64) + relu + maxpool2 -- IMAGE-PAIR fp32x2,
// weight-hoisted vertical-strip walk.  (R12 winner, unchanged)
// =========================================================================
#define CONV2_SMEM (65536 + 147456 + 256)
__global__ __launch_bounds__(512, 1) void conv2_kernel(
    const float* __restrict__ w, const float* __restrict__ bias)
{
    extern __shared__ float sm2[];
    u64*   sdin64 = (u64*)sm2;                   // [32 ic][256 pos] (img0,img1)
    u64*   swd64  = (u64*)(sm2 + 16384);         // [ic*9+t][64 ch] (w,w)
    float* sb     = sm2 + 16384 + 36864;         // 64

    const int pair = blockIdx.x;
    const int img0 = pair * 2, img1 = img0 + 1;
    const int tid  = threadIdx.x;

    for (int i = tid; i < 8192; i += 512) sdin64[i] = 0ull;
    for (int idx = tid; idx < 18432; idx += 512) {
        int c = idx & 63, f = idx >> 6;          // f = ic*9 + t
        int ic = f / 9, t = f % 9;
        float v = w[(c * 32 + ic) * 9 + t];
        swd64[f * 64 + c] = pack2(v, v);
    }
    if (tid < 64) sb[tid] = bias[tid];
    __syncthreads();
    for (int i = tid; i < 32 * 196; i += 512) {
        int ic = i / 196, p = i % 196;
        int y = p / 14, xx = p % 14;
        float v0 = g_h1[img0 * 6272 + i];
        float v1 = g_h1[img1 * 6272 + i];
        sdin64[ic * 256 + (y + 1) * 16 + xx + 1] = pack2(v0, v1);
    }
    __syncthreads();

    const int wd   = tid >> 5;          // 0..15 (warps 14,15 idle)
    const int lane = tid & 31;
    if (wd < 14) {
        const int slot = wd % 7;        // ox column
        const int half = wd / 7;
        const int c    = half * 32 + lane;
        const float bv = sb[c];
        const int ix   = 2 * slot;

        u64 acc[7][4];
        #pragma unroll
        for (int s = 0; s < 7; s++)
            #pragma unroll
            for (int p = 0; p < 4; p++) acc[s][p] = 0ull;

        for (int ic = 0; ic < 32; ic++) {
            const u64* base = sdin64 + ic * 256;

            u64 wv[9];
            #pragma unroll
            for (int t = 0; t < 9; t++)
                wv[t] = swd64[(ic * 9 + t) * 64 + c];

            u64 pa[4][4];
            #pragma unroll
            for (int r = 0; r < 4; r++) {
                ulonglong2 q0 = *(const ulonglong2*)(base + r * 16 + ix);
                ulonglong2 q1 = *(const ulonglong2*)(base + r * 16 + ix + 2);
                pa[r][0] = q0.x; pa[r][1] = q0.y;
                pa[r][2] = q1.x; pa[r][3] = q1.y;
            }

            #pragma unroll
            for (int s = 0; s < 7; s++) {
                #pragma unroll
                for (int ky = 0; ky < 3; ky++) {
                    #pragma unroll
                    for (int kx = 0; kx < 3; kx++) {
                        u64 wt = wv[ky * 3 + kx];
                        acc[s][0] = ffma2(pa[ky][kx],         wt, acc[s][0]);
                        acc[s][1] = ffma2(pa[ky][kx + 1],     wt, acc[s][1]);
                        acc[s][2] = ffma2(pa[ky + 1][kx],     wt, acc[s][2]);
                        acc[s][3] = ffma2(pa[ky + 1][kx + 1], wt, acc[s][3]);
                    }
                }
                if (s < 6) {
                    #pragma unroll
                    for (int cc = 0; cc < 4; cc++) {
                        pa[0][cc] = pa[2][cc];
                        pa[1][cc] = pa[3][cc];
                    }
                    const int r2 = 2 * s + 4;
                    ulonglong2 q0 = *(const ulonglong2*)(base + r2 * 16 + ix);
                    ulonglong2 q1 = *(const ulonglong2*)(base + r2 * 16 + ix + 2);
                    ulonglong2 q2 = *(const ulonglong2*)(base + (r2 + 1) * 16 + ix);
                    ulonglong2 q3 = *(const ulonglong2*)(base + (r2 + 1) * 16 + ix + 2);
                    pa[2][0] = q0.x; pa[2][1] = q0.y; pa[2][2] = q1.x; pa[2][3] = q1.y;
                    pa[3][0] = q2.x; pa[3][1] = q2.y; pa[3][2] = q3.x; pa[3][3] = q3.y;
                }
            }
        }

        #pragma unroll
        for (int s = 0; s < 7; s++) {
            const int pos = 7 * s + slot;
            float a0[4], a1[4];
            #pragma unroll
            for (int p = 0; p < 4; p++) unpack2(acc[s][p], a0[p], a1[p]);
            float m0 = fmaxf(fmaxf(a0[0], a0[1]), fmaxf(a0[2], a0[3])) + bv;
            float m1 = fmaxf(fmaxf(a1[0], a1[1]), fmaxf(a1[2], a1[3])) + bv;
            g_h2[img0 * 3136 + c * 49 + pos] = fmaxf(m0, 0.f);
            g_h2[img1 * 3136 + c * 49 + pos] = fmaxf(m1, 0.f);
        }
    }
}

// =========================================================================
// Kernel 3: fc, weight-stationary. 128 blocks x 4 images (86% chip).
// =========================================================================
#define FC_IMS   4
#define FC_CHUNK 392
#define FC_WPAD  66
#define FC_SMEM  ((FC_IMS * 3136 + FC_CHUNK * FC_WPAD) * 4)
__global__ __launch_bounds__(256) void fc_kernel(
    const float* __restrict__ fcw, const float* __restrict__ fcb)
{
    extern __shared__ float smf[];
    float* sact = smf;                       // [4][3136]
    float* swc  = smf + FC_IMS * 3136;       // [392][66] transposed chunk

    const int tid  = threadIdx.x;
    const int img0 = blockIdx.x * FC_IMS;

    for (int idx = tid; idx < FC_IMS * 3136; idx += 256)
        sact[idx] = g_h2[img0 * 3136 + idx];

    const int o2 = (tid & 31) * 2;
    const int q  = tid >> 5;

    u64 acc[FC_IMS];
    #pragma unroll
    for (int im = 0; im < FC_IMS; im++) acc[im] = 0ull;

    for (int ch = 0; ch < 8; ch++) {
        __syncthreads();
        for (int idx = tid; idx < 64 * FC_CHUNK; idx += 256) {
            int o = idx / FC_CHUNK, i = idx % FC_CHUNK;
            swc[i * FC_WPAD + o] = fcw[(size_t)o * 3136 + ch * FC_CHUNK + i];
        }
        __syncthreads();

        const int ibase = q * 49;
        #pragma unroll 7
        for (int t = 0; t < 49; t++) {
            int i = ibase + t;
            u64 wv = *(const u64*)(swc + i * FC_WPAD + o2);
            int gi = ch * FC_CHUNK + i;
            #pragma unroll
            for (int im = 0; im < FC_IMS; im++) {
                float a = sact[im * 3136 + gi];
                acc[im] = ffma2(pack2(a, a), wv, acc[im]);
            }
        }
    }
    __syncthreads();

    float* sred = swc;   // [8 q][4 im][64]
    #pragma unroll
    for (int im = 0; im < FC_IMS; im++) {
        float a0, a1;
        unpack2(acc[im], a0, a1);
        sred[q * (FC_IMS * 64) + im * 64 + o2]     = a0;
        sred[q * (FC_IMS * 64) + im * 64 + o2 + 1] = a1;
    }
    __syncthreads();
    for (int idx = tid; idx < FC_IMS * 64; idx += 256) {
        int im = idx >> 6, o = idx & 63;
        float s = 0.f;
        #pragma unroll
        for (int qq = 0; qq < 8; qq++) s += sred[qq * (FC_IMS * 64) + idx];
        g_feat[(img0 + im) * 64 + o] = fmaxf(s + fcb[o], 0.f);
    }
}

// =========================================================================
// Kernel 4: Eq3to3 + relu + mean(ijk). Warp-tile rank-1 outer product.
// R13: vectorized d-loop loads (aj 2x LDS.128, ak 2x LDS.128 -> 5 LDS/d
// instead of 13) + epilogue gk/gj hoisted across jj.
// =========================================================================
#define EQ_NT 320
#define EQ_SMEM ((2304 + 64 + 3*4352 + 2*2048 + 64 + 640) * 4)
__global__ __launch_bounds__(EQ_NT, 2) void eq_kernel(
    const float* __restrict__ eqw, const float* __restrict__ eqb)
{
    extern __shared__ float sm[];
    float* sat  = sm;            // [d][k] pad 36 : 2304
    float* sAb  = sat + 2304;    // 64
    float* sV   = sAb + 64;      // [d][e] pad 68 : 4352
    float* sCk  = sV  + 4352;
    float* sCj  = sCk + 4352;
    float* sgk  = sCj + 4352;    // [k][e] : 2048
    float* sgj  = sgk + 2048;    // [j][e] : 2048
    float* ssb  = sgj + 2048;    // 64
    float* sred = ssb + 64;      // [10 warps][64]

    const int b   = blockIdx.x >> 5;
    const int ii  = blockIdx.x & 31;
    const int tid = threadIdx.x;

    const float* fb = g_feat + b * KK * HID;
    for (int idx = tid; idx < 2048; idx += EQ_NT) {
        int k = idx >> 6, d = idx & 63;
        sat[d * 36 + k] = fb[idx];
    }
    __syncthreads();
    if (tid < 64) {
        const float* row = sat + tid * 36;
        float s = 0.f;
        #pragma unroll
        for (int k = 0; k < 32; k++) s += row[k];
        sAb[tid] = s * (1.0f / 32.0f);
    }
    __syncthreads();

    for (int idx = tid; idx < 4096; idx += EQ_NT) {
        int d = idx >> 6, e = idx & 63;
        const float4* wp = (const float4*)(eqw + (size_t)idx * 8);
        float4 wA = wp[0];   // w0 w1 w2 w3
        float4 wB = wp[1];   // w4 w5 w6 w7
        float ai = sat[d * 36 + ii], ab = sAb[d];
        sV [d * 68 + e] = wA.x * ai + wA.y * ab;
        sCk[d * 68 + e] = ab * (wA.z * ai + wB.x * ab);
        sCj[d * 68 + e] = ab * (wA.w * ai + wB.y * ab);
    }
    if (tid < 64) {
        int e = tid;
        float s = 0.f;
        for (int d = 0; d < 64; d++) {
            float ab = sAb[d];
            float2 w67 = *(const float2*)(eqw + ((size_t)(d * 64 + e)) * 8 + 6);
            s += ab * ab * (w67.x * sat[d * 36 + ii] + w67.y * ab);
        }
        ssb[e] = s + eqb[e];
    }
    __syncthreads();

    for (int idx = tid; idx < 2048; idx += EQ_NT) {
        int k = idx >> 6, e = idx & 63;
        float s1 = 0.f, s2 = 0.f;
        #pragma unroll 8
        for (int d = 0; d < 64; d++) {
            float ak = sat[d * 36 + k];
            s1 += sCk[d * 68 + e] * ak;
            s2 += sCj[d * 68 + e] * ak;
        }
        sgk[k * 64 + e] = s1;
        sgj[k * 64 + e] = s2;
    }
    __syncthreads();

    const int w    = tid >> 5;
    const int lane = tid & 31;

    const u64 JT = 0x3221110000ull;
    const u64 KT = 0x3323213210ull;
    const int jt = (int)((JT >> (4 * w)) & 15);
    const int kt = (int)((KT >> (4 * w)) & 15);
    const int j0 = jt * 8;
    const int k0 = kt * 8;
    const bool diag = (jt == kt);

    float esum0 = 0.f, esum1 = 0.f;

    #pragma unroll
    for (int pass = 0; pass < 2; pass++) {
        const int e = lane + 32 * pass;

        u64 acc[8][4];
        #pragma unroll
        for (int jj = 0; jj < 8; jj++)
            #pragma unroll
            for (int kp = 0; kp < 4; kp++) acc[jj][kp] = 0ull;

        for (int d = 0; d < 64; d++) {
            const float* rd = sat + d * 36;
            float vl = sV[d * 68 + e];                       // lane-consecutive
            float4 ajA = *(const float4*)(rd + j0);          // broadcast LDS.128
            float4 ajB = *(const float4*)(rd + j0 + 4);      // broadcast LDS.128
            ulonglong2 akA = *(const ulonglong2*)(rd + k0);      // broadcast
            ulonglong2 akB = *(const ulonglong2*)(rd + k0 + 4);  // broadcast
            float aj[8] = {ajA.x, ajA.y, ajA.z, ajA.w, ajB.x, ajB.y, ajB.z, ajB.w};
            u64 ak[4] = {akA.x, akA.y, akB.x, akB.y};

            #pragma unroll
            for (int jj = 0; jj < 8; jj++) {
                float tv = aj[jj] * vl;
                u64 tp = pack2(tv, tv);
                acc[jj][0] = ffma2(tp, ak[0], acc[jj][0]);
                acc[jj][1] = ffma2(tp, ak[1], acc[jj][1]);
                acc[jj][2] = ffma2(tp, ak[2], acc[jj][2]);
                acc[jj][3] = ffma2(tp, ak[3], acc[jj][3]);
            }
        }

        // epilogue: gk/gj for the 8 k's hoisted across jj
        const float sbv = ssb[e];
        float gkk[8], gjk[8];
        #pragma unroll
        for (int u = 0; u < 8; u++) {
            gkk[u] = sgk[(k0 + u) * 64 + e];
            gjk[u] = sgj[(k0 + u) * 64 + e];
        }
        float es = 0.f;
        #pragma unroll
        for (int jj = 0; jj < 8; jj++) {
            const int j = j0 + jj;
            const float gjj = sgj[j * 64 + e];
            const float gkj = sgk[j * 64 + e];
            #pragma unroll
            for (int kp = 0; kp < 4; kp++) {
                float a0, a1;
                unpack2(acc[jj][kp], a0, a1);
                const int ua = 2 * kp, ub = ua + 1;
                const int ka = k0 + ua, kb = k0 + ub;
                float p0 = a0 + gjj + gkk[ua] + sbv;
                float q0 = a0 + gjk[ua] + gkj + sbv;
                float p1 = a1 + gjj + gkk[ub] + sbv;
                float q1 = a1 + gjk[ub] + gkj + sbv;
                if (!diag || ka >= j) es += fmaxf(p0, 0.f);
                if (!diag || ka >  j) es += fmaxf(q0, 0.f);
                if (!diag || kb >= j) es += fmaxf(p1, 0.f);
                if (!diag || kb >  j) es += fmaxf(q1, 0.f);
            }
        }
        if (pass == 0) esum0 = es; else esum1 = es;
    }

    sred[w * 64 + lane]      = esum0;
    sred[w * 64 + lane + 32] = esum1;
    __syncthreads();
    if (tid < 64) {
        float s = 0.f;
        #pragma unroll
        for (int g = 0; g < 10; g++) s += sred[g * 64 + tid];
        g_part[blockIdx.x * 64 + tid] = s;
    }
}

// =========================================================================
// Kernel 5: final
// =========================================================================
__global__ __launch_bounds__(64) void final_kernel(
    const float* __restrict__ outw, const float* __restrict__ outb,
    float* __restrict__ out)
{
    __shared__ float red[64];
    const int b = blockIdx.x, e = threadIdx.x;
    float s = 0.f;
    #pragma unroll
    for (int i = 0; i < 32; i++) s += g_part[(b * 32 + i) * 64 + e];
    float x8 = s * (1.0f / 32768.0f);
    red[e] = fmaxf(x8, 0.f) * outw[e];
    __syncthreads();
    #pragma unroll
    for (int off = 32; off; off >>= 1) {
        if (e < off) red[e] += red[e + off];
        __syncthreads();
    }
    if (e == 0) out[b] = red[0] + outb[0];
}

// =========================================================================
extern "C" void kernel_launch(void* const* d_in, const int* in_sizes, int n_in,
                              void* d_out, int out_size)
{
    const float* x    = (const float*)d_in[0];
    const float* c1w  = (const float*)d_in[1];
    const float* c1b  = (const float*)d_in[2];
    const float* c2w  = (const float*)d_in[3];
    const float* c2b  = (const float*)d_in[4];
    const float* fcw  = (const float*)d_in[5];
    const float* fcb  = (const float*)d_in[6];
    const float* eqw  = (const float*)d_in[7];
    const float* eqb  = (const float*)d_in[8];
    const float* outw = (const float*)d_in[9];
    const float* outb = (const float*)d_in[10];
    float* out = (float*)d_out;

    cudaFuncSetAttribute(conv2_kernel, cudaFuncAttributeMaxDynamicSharedMemorySize, CONV2_SMEM);
    cudaFuncSetAttribute(fc_kernel,    cudaFuncAttributeMaxDynamicSharedMemorySize, FC_SMEM);
    cudaFuncSetAttribute(eq_kernel,    cudaFuncAttributeMaxDynamicSharedMemorySize, EQ_SMEM);

    conv1_kernel<<<NIMG, 256>>>(x, c1w, c1b);
    conv2_kernel<<<NIMG / 2, 512, CONV2_SMEM>>>(c2w, c2b);
    fc_kernel<<<128, 256, FC_SMEM>>>(fcw, fcb);
    eq_kernel<<<NIMG, EQ_NT, EQ_SMEM>>>(eqw, eqb);
    final_kernel<<<BB, 64>>>(outw, outb, out);
}

// round 14
// speedup vs baseline: 1.0642x; 1.0642x over previous
#include <cuda_runtime.h>
#include <cuda_bf16.h>
#include <math.h>

#define BB   16
#define KK   32
#define HH   28
#define WW   28
#define HID  64
#define OUT  64
#define NIMG (BB*KK)          // 512

typedef unsigned long long u64;

// ---------------- scratch ----------------
__device__ float g_h1[NIMG * 32 * 14 * 14];
__device__ float g_h2[NIMG * 64 * 7 * 7];
__device__ float g_feat[NIMG * HID];
__device__ float g_part[NIMG * OUT];

// ---------------- packed fp32x2 helpers ----------------
__device__ __forceinline__ u64 pack2(float x, float y) {
    u64 r; asm("mov.b64 %0,{%1,%2};" : "=l"(r) : "f"(x), "f"(y)); return r;
}
__device__ __forceinline__ void unpack2(u64 p, float& x, float& y) {
    asm("mov.b64 {%0,%1},%2;" : "=f"(x), "=f"(y) : "l"(p));
}
__device__ __forceinline__ u64 ffma2(u64 a, u64 b, u64 c) {
    u64 d; asm("fma.rn.f32x2 %0,%1,%2,%3;" : "=l"(d) : "l"(a), "l"(b), "l"(c)); return d;
}

// =========================================================================
// Kernel 1: conv1 (1->32, 3x3 SAME) + relu + maxpool2
// =========================================================================
__global__ __launch_bounds__(256) void conv1_kernel(
    const float* __restrict__ x, const float* __restrict__ w,
    const float* __restrict__ bias)
{
    __shared__ float sin1[30 * 30];
    __shared__ float sw1[32 * 9];
    __shared__ float sb1[32];

    const int img = blockIdx.x;
    const int tid = threadIdx.x;

    for (int i = tid; i < 900; i += 256) sin1[i] = 0.f;
    for (int i = tid; i < 288; i += 256) sw1[i] = w[i];
    if (tid < 32) sb1[tid] = bias[tid];
    __syncthreads();
    for (int i = tid; i < 784; i += 256) {
        int y = i / 28, xx = i % 28;
        sin1[(y + 1) * 30 + xx + 1] = x[img * 784 + i];
    }
    __syncthreads();

    for (int item = tid; item < 32 * 196; item += 256) {
        int c = item / 196, p = item % 196;
        int oy = p / 14, ox = p % 14;
        const float* wp = sw1 + c * 9;
        const float bv = sb1[c];
        float m = 0.f;
        #pragma unroll
        for (int py = 0; py < 2; py++) {
            #pragma unroll
            for (int px = 0; px < 2; px++) {
                int r = 2 * oy + py, col = 2 * ox + px;
                float s = bv;
                #pragma unroll
                for (int ky = 0; ky < 3; ky++)
                    #pragma unroll
                    for (int kx = 0; kx < 3; kx++)
                        s += sin1[(r + ky) * 30 + col + kx] * wp[ky * 3 + kx];
                m = fmaxf(m, s);
            }
        }
        g_h1[img * (32 * 196) + item] = m;
    }
}

// =========================================================================
// Kernel 2: conv2 (32->64) + relu + maxpool2 -- IMAGE-PAIR fp32x2,
// weight-hoisted vertical-strip walk.  (R12 winner, unchanged)
// =========================================================================
#define CONV2_SMEM (65536 + 147456 + 256)
__global__ __launch_bounds__(512, 1) void conv2_kernel(
    const float* __restrict__ w, const float* __restrict__ bias)
{
    extern __shared__ float sm2[];
    u64*   sdin64 = (u64*)sm2;                   // [32 ic][256 pos] (img0,img1)
    u64*   swd64  = (u64*)(sm2 + 16384);         // [ic*9+t][64 ch] (w,w)
    float* sb     = sm2 + 16384 + 36864;         // 64

    const int pair = blockIdx.x;
    const int img0 = pair * 2, img1 = img0 + 1;
    const int tid  = threadIdx.x;

    for (int i = tid; i < 8192; i += 512) sdin64[i] = 0ull;
    for (int idx = tid; idx < 18432; idx += 512) {
        int c = idx & 63, f = idx >> 6;          // f = ic*9 + t
        int ic = f / 9, t = f % 9;
        float v = w[(c * 32 + ic) * 9 + t];
        swd64[f * 64 + c] = pack2(v, v);
    }
    if (tid < 64) sb[tid] = bias[tid];
    __syncthreads();
    for (int i = tid; i < 32 * 196; i += 512) {
        int ic = i / 196, p = i % 196;
        int y = p / 14, xx = p % 14;
        float v0 = g_h1[img0 * 6272 + i];
        float v1 = g_h1[img1 * 6272 + i];
        sdin64[ic * 256 + (y + 1) * 16 + xx + 1] = pack2(v0, v1);
    }
    __syncthreads();

    const int wd   = tid >> 5;          // 0..15 (warps 14,15 idle)
    const int lane = tid & 31;
    if (wd < 14) {
        const int slot = wd % 7;        // ox column
        const int half = wd / 7;
        const int c    = half * 32 + lane;
        const float bv = sb[c];
        const int ix   = 2 * slot;

        u64 acc[7][4];
        #pragma unroll
        for (int s = 0; s < 7; s++)
            #pragma unroll
            for (int p = 0; p < 4; p++) acc[s][p] = 0ull;

        for (int ic = 0; ic < 32; ic++) {
            const u64* base = sdin64 + ic * 256;

            u64 wv[9];
            #pragma unroll
            for (int t = 0; t < 9; t++)
                wv[t] = swd64[(ic * 9 + t) * 64 + c];

            u64 pa[4][4];
            #pragma unroll
            for (int r = 0; r < 4; r++) {
                ulonglong2 q0 = *(const ulonglong2*)(base + r * 16 + ix);
                ulonglong2 q1 = *(const ulonglong2*)(base + r * 16 + ix + 2);
                pa[r][0] = q0.x; pa[r][1] = q0.y;
                pa[r][2] = q1.x; pa[r][3] = q1.y;
            }

            #pragma unroll
            for (int s = 0; s < 7; s++) {
                #pragma unroll
                for (int ky = 0; ky < 3; ky++) {
                    #pragma unroll
                    for (int kx = 0; kx < 3; kx++) {
                        u64 wt = wv[ky * 3 + kx];
                        acc[s][0] = ffma2(pa[ky][kx],         wt, acc[s][0]);
                        acc[s][1] = ffma2(pa[ky][kx + 1],     wt, acc[s][1]);
                        acc[s][2] = ffma2(pa[ky + 1][kx],     wt, acc[s][2]);
                        acc[s][3] = ffma2(pa[ky + 1][kx + 1], wt, acc[s][3]);
                    }
                }
                if (s < 6) {
                    #pragma unroll
                    for (int cc = 0; cc < 4; cc++) {
                        pa[0][cc] = pa[2][cc];
                        pa[1][cc] = pa[3][cc];
                    }
                    const int r2 = 2 * s + 4;
                    ulonglong2 q0 = *(const ulonglong2*)(base + r2 * 16 + ix);
                    ulonglong2 q1 = *(const ulonglong2*)(base + r2 * 16 + ix + 2);
                    ulonglong2 q2 = *(const ulonglong2*)(base + (r2 + 1) * 16 + ix);
                    ulonglong2 q3 = *(const ulonglong2*)(base + (r2 + 1) * 16 + ix + 2);
                    pa[2][0] = q0.x; pa[2][1] = q0.y; pa[2][2] = q1.x; pa[2][3] = q1.y;
                    pa[3][0] = q2.x; pa[3][1] = q2.y; pa[3][2] = q3.x; pa[3][3] = q3.y;
                }
            }
        }

        #pragma unroll
        for (int s = 0; s < 7; s++) {
            const int pos = 7 * s + slot;
            float a0[4], a1[4];
            #pragma unroll
            for (int p = 0; p < 4; p++) unpack2(acc[s][p], a0[p], a1[p]);
            float m0 = fmaxf(fmaxf(a0[0], a0[1]), fmaxf(a0[2], a0[3])) + bv;
            float m1 = fmaxf(fmaxf(a1[0], a1[1]), fmaxf(a1[2], a1[3])) + bv;
            g_h2[img0 * 3136 + c * 49 + pos] = fmaxf(m0, 0.f);
            g_h2[img1 * 3136 + c * 49 + pos] = fmaxf(m1, 0.f);
        }
    }
}

// =========================================================================
// Kernel 3: fc, weight-stationary. 64 blocks x 8 images.  (R12 winner)
// =========================================================================
#define FC_CHUNK 392
#define FC_WPAD  66
#define FC_SMEM  ((8 * 3136 + FC_CHUNK * FC_WPAD) * 4)
__global__ __launch_bounds__(256) void fc_kernel(
    const float* __restrict__ fcw, const float* __restrict__ fcb)
{
    extern __shared__ float smf[];
    float* sact = smf;                  // [8][3136]
    float* swc  = smf + 8 * 3136;       // [392][66] transposed chunk

    const int tid  = threadIdx.x;
    const int img0 = blockIdx.x * 8;

    for (int idx = tid; idx < 8 * 3136; idx += 256)
        sact[idx] = g_h2[img0 * 3136 + idx];

    const int o2 = (tid & 31) * 2;
    const int q  = tid >> 5;

    u64 acc[8];
    #pragma unroll
    for (int im = 0; im < 8; im++) acc[im] = 0ull;

    for (int ch = 0; ch < 8; ch++) {
        __syncthreads();
        for (int idx = tid; idx < 64 * FC_CHUNK; idx += 256) {
            int o = idx / FC_CHUNK, i = idx % FC_CHUNK;
            swc[i * FC_WPAD + o] = fcw[(size_t)o * 3136 + ch * FC_CHUNK + i];
        }
        __syncthreads();

        const int ibase = q * 49;
        #pragma unroll 7
        for (int t = 0; t < 49; t++) {
            int i = ibase + t;
            u64 wv = *(const u64*)(swc + i * FC_WPAD + o2);
            int gi = ch * FC_CHUNK + i;
            #pragma unroll
            for (int im = 0; im < 8; im++) {
                float a = sact[im * 3136 + gi];
                acc[im] = ffma2(pack2(a, a), wv, acc[im]);
            }
        }
    }
    __syncthreads();

    float* sred = swc;
    #pragma unroll
    for (int im = 0; im < 8; im++) {
        float a0, a1;
        unpack2(acc[im], a0, a1);
        sred[q * 512 + im * 64 + o2]     = a0;
        sred[q * 512 + im * 64 + o2 + 1] = a1;
    }
    __syncthreads();
    for (int idx = tid; idx < 512; idx += 256) {
        int im = idx >> 6, o = idx & 63;
        float s = 0.f;
        #pragma unroll
        for (int qq = 0; qq < 8; qq++) s += sred[qq * 512 + idx];
        g_feat[(img0 + im) * 64 + o] = fmaxf(s + fcb[o], 0.f);
    }
}

// =========================================================================
// Kernel 4: Eq3to3 + relu + mean(ijk). Warp-tile rank-1 outer product.
// R14: R13 vectorized d-loop + parallelized ssb phase (256 threads in
// 4 d-quarters instead of 64 threads x 64 d).
// =========================================================================
#define EQ_NT 320
#define EQ_SMEM ((2304 + 64 + 3*4352 + 2*2048 + 64 + 640) * 4)
__global__ __launch_bounds__(EQ_NT, 2) void eq_kernel(
    const float* __restrict__ eqw, const float* __restrict__ eqb)
{
    extern __shared__ float sm[];
    float* sat  = sm;            // [d][k] pad 36 : 2304
    float* sAb  = sat + 2304;    // 64
    float* sV   = sAb + 64;      // [d][e] pad 68 : 4352
    float* sCk  = sV  + 4352;
    float* sCj  = sCk + 4352;
    float* sgk  = sCj + 4352;    // [k][e] : 2048
    float* sgj  = sgk + 2048;    // [j][e] : 2048
    float* ssb  = sgj + 2048;    // 64
    float* sred = ssb + 64;      // [10 warps][64] (also ssb partials temp)

    const int b   = blockIdx.x >> 5;
    const int ii  = blockIdx.x & 31;
    const int tid = threadIdx.x;

    const float* fb = g_feat + b * KK * HID;
    for (int idx = tid; idx < 2048; idx += EQ_NT) {
        int k = idx >> 6, d = idx & 63;
        sat[d * 36 + k] = fb[idx];
    }
    __syncthreads();
    if (tid < 64) {
        const float* row = sat + tid * 36;
        float s = 0.f;
        #pragma unroll
        for (int k = 0; k < 32; k++) s += row[k];
        sAb[tid] = s * (1.0f / 32.0f);
    }
    __syncthreads();

    // V/Ck/Cj build (all threads) + ssb partials (first 256 threads)
    for (int idx = tid; idx < 4096; idx += EQ_NT) {
        int d = idx >> 6, e = idx & 63;
        const float4* wp = (const float4*)(eqw + (size_t)idx * 8);
        float4 wA = wp[0];   // w0 w1 w2 w3
        float4 wB = wp[1];   // w4 w5 w6 w7
        float ai = sat[d * 36 + ii], ab = sAb[d];
        sV [d * 68 + e] = wA.x * ai + wA.y * ab;
        sCk[d * 68 + e] = ab * (wA.z * ai + wB.x * ab);
        sCj[d * 68 + e] = ab * (wA.w * ai + wB.y * ab);
    }
    if (tid < 256) {
        const int e  = tid & 63;
        const int dq = tid >> 6;        // 0..3, 16 d each
        float s = 0.f;
        #pragma unroll 4
        for (int d = dq * 16; d < dq * 16 + 16; d++) {
            float ab = sAb[d];
            float2 w67 = *(const float2*)(eqw + ((size_t)(d * 64 + e)) * 8 + 6);
            s += ab * ab * (w67.x * sat[d * 36 + ii] + w67.y * ab);
        }
        sred[dq * 64 + e] = s;
    }
    __syncthreads();

    // combine ssb (tid<64) + gk/gj (all threads), same phase
    if (tid < 64)
        ssb[tid] = sred[tid] + sred[64 + tid] + sred[128 + tid]
                 + sred[192 + tid] + eqb[tid];
    for (int idx = tid; idx < 2048; idx += EQ_NT) {
        int k = idx >> 6, e = idx & 63;
        float s1 = 0.f, s2 = 0.f;
        #pragma unroll 8
        for (int d = 0; d < 64; d++) {
            float ak = sat[d * 36 + k];
            s1 += sCk[d * 68 + e] * ak;
            s2 += sCj[d * 68 + e] * ak;
        }
        sgk[k * 64 + e] = s1;
        sgj[k * 64 + e] = s2;
    }
    __syncthreads();

    const int w    = tid >> 5;
    const int lane = tid & 31;

    const u64 JT = 0x3221110000ull;
    const u64 KT = 0x3323213210ull;
    const int jt = (int)((JT >> (4 * w)) & 15);
    const int kt = (int)((KT >> (4 * w)) & 15);
    const int j0 = jt * 8;
    const int k0 = kt * 8;
    const bool diag = (jt == kt);

    float esum0 = 0.f, esum1 = 0.f;

    #pragma unroll
    for (int pass = 0; pass < 2; pass++) {
        const int e = lane + 32 * pass;

        u64 acc[8][4];
        #pragma unroll
        for (int jj = 0; jj < 8; jj++)
            #pragma unroll
            for (int kp = 0; kp < 4; kp++) acc[jj][kp] = 0ull;

        for (int d = 0; d < 64; d++) {
            const float* rd = sat + d * 36;
            float vl = sV[d * 68 + e];                       // lane-consecutive
            float4 ajA = *(const float4*)(rd + j0);          // broadcast LDS.128
            float4 ajB = *(const float4*)(rd + j0 + 4);      // broadcast LDS.128
            ulonglong2 akA = *(const ulonglong2*)(rd + k0);      // broadcast
            ulonglong2 akB = *(const ulonglong2*)(rd + k0 + 4);  // broadcast
            float aj[8] = {ajA.x, ajA.y, ajA.z, ajA.w, ajB.x, ajB.y, ajB.z, ajB.w};
            u64 ak[4] = {akA.x, akA.y, akB.x, akB.y};

            #pragma unroll
            for (int jj = 0; jj < 8; jj++) {
                float tv = aj[jj] * vl;
                u64 tp = pack2(tv, tv);
                acc[jj][0] = ffma2(tp, ak[0], acc[jj][0]);
                acc[jj][1] = ffma2(tp, ak[1], acc[jj][1]);
                acc[jj][2] = ffma2(tp, ak[2], acc[jj][2]);
                acc[jj][3] = ffma2(tp, ak[3], acc[jj][3]);
            }
        }

        // epilogue: gk/gj for the 8 k's hoisted across jj
        const float sbv = ssb[e];
        float gkk[8], gjk[8];
        #pragma unroll
        for (int u = 0; u < 8; u++) {
            gkk[u] = sgk[(k0 + u) * 64 + e];
            gjk[u] = sgj[(k0 + u) * 64 + e];
        }
        float es = 0.f;
        #pragma unroll
        for (int jj = 0; jj < 8; jj++) {
            const int j = j0 + jj;
            const float gjj = sgj[j * 64 + e];
            const float gkj = sgk[j * 64 + e];
            #pragma unroll
            for (int kp = 0; kp < 4; kp++) {
                float a0, a1;
                unpack2(acc[jj][kp], a0, a1);
                const int ua = 2 * kp, ub = ua + 1;
                const int ka = k0 + ua, kb = k0 + ub;
                float p0 = a0 + gjj + gkk[ua] + sbv;
                float q0 = a0 + gjk[ua] + gkj + sbv;
                float p1 = a1 + gjj + gkk[ub] + sbv;
                float q1 = a1 + gjk[ub] + gkj + sbv;
                if (!diag || ka >= j) es += fmaxf(p0, 0.f);
                if (!diag || ka >  j) es += fmaxf(q0, 0.f);
                if (!diag || kb >= j) es += fmaxf(p1, 0.f);
                if (!diag || kb >  j) es += fmaxf(q1, 0.f);
            }
        }
        if (pass == 0) esum0 = es; else esum1 = es;
    }

    sred[w * 64 + lane]      = esum0;
    sred[w * 64 + lane + 32] = esum1;
    __syncthreads();
    if (tid < 64) {
        float s = 0.f;
        #pragma unroll
        for (int g = 0; g < 10; g++) s += sred[g * 64 + tid];
        g_part[blockIdx.x * 64 + tid] = s;
    }
}

// =========================================================================
// Kernel 5: final
// =========================================================================
__global__ __launch_bounds__(64) void final_kernel(
    const float* __restrict__ outw, const float* __restrict__ outb,
    float* __restrict__ out)
{
    __shared__ float red[64];
    const int b = blockIdx.x, e = threadIdx.x;
    float s = 0.f;
    #pragma unroll
    for (int i = 0; i < 32; i++) s += g_part[(b * 32 + i) * 64 + e];
    float x8 = s * (1.0f / 32768.0f);
    red[e] = fmaxf(x8, 0.f) * outw[e];
    __syncthreads();
    #pragma unroll
    for (int off = 32; off; off >>= 1) {
        if (e < off) red[e] += red[e + off];
        __syncthreads();
    }
    if (e == 0) out[b] = red[0] + outb[0];
}

// =========================================================================
extern "C" void kernel_launch(void* const* d_in, const int* in_sizes, int n_in,
                              void* d_out, int out_size)
{
    const float* x    = (const float*)d_in[0];
    const float* c1w  = (const float*)d_in[1];
    const float* c1b  = (const float*)d_in[2];
    const float* c2w  = (const float*)d_in[3];
    const float* c2b  = (const float*)d_in[4];
    const float* fcw  = (const float*)d_in[5];
    const float* fcb  = (const float*)d_in[6];
    const float* eqw  = (const float*)d_in[7];
    const float* eqb  = (const float*)d_in[8];
    const float* outw = (const float*)d_in[9];
    const float* outb = (const float*)d_in[10];
    float* out = (float*)d_out;

    cudaFuncSetAttribute(conv2_kernel, cudaFuncAttributeMaxDynamicSharedMemorySize, CONV2_SMEM);
    cudaFuncSetAttribute(fc_kernel,    cudaFuncAttributeMaxDynamicSharedMemorySize, FC_SMEM);
    cudaFuncSetAttribute(eq_kernel,    cudaFuncAttributeMaxDynamicSharedMemorySize, EQ_SMEM);

    conv1_kernel<<<NIMG, 256>>>(x, c1w, c1b);
    conv2_kernel<<<NIMG / 2, 512, CONV2_SMEM>>>(c2w, c2b);
    fc_kernel<<<64, 256, FC_SMEM>>>(fcw, fcb);
    eq_kernel<<<NIMG, EQ_NT, EQ_SMEM>>>(eqw, eqb);
    final_kernel<<<BB, 64>>>(outw, outb, out);
}

// round 15
// speedup vs baseline: 1.2358x; 1.1613x over previous
#include <cuda_runtime.h>
#include <cuda_bf16.h>
#include <math.h>

#define BB   16
#define KK   32
#define HH   28
#define WW   28
#define HID  64
#define OUT  64
#define NIMG (BB*KK)          // 512

typedef unsigned long long u64;

// ---------------- scratch ----------------
__device__ float g_h2[NIMG * 64 * 7 * 7];
__device__ float g_feat[NIMG * HID];
__device__ float g_part[NIMG * OUT];

// ---------------- packed fp32x2 helpers ----------------
__device__ __forceinline__ u64 pack2(float x, float y) {
    u64 r; asm("mov.b64 %0,{%1,%2};" : "=l"(r) : "f"(x), "f"(y)); return r;
}
__device__ __forceinline__ void unpack2(u64 p, float& x, float& y) {
    asm("mov.b64 {%0,%1},%2;" : "=f"(x), "=f"(y) : "l"(p));
}
__device__ __forceinline__ u64 ffma2(u64 a, u64 b, u64 c) {
    u64 d; asm("fma.rn.f32x2 %0,%1,%2,%3;" : "=l"(d) : "l"(a), "l"(b), "l"(c)); return d;
}

// =========================================================================
// Kernel A: FUSED conv1+pool+relu  ->  conv2+pool+relu, per IMAGE PAIR.
// conv1 output is written directly into conv2's interleaved smem input
// (no g_h1 gmem roundtrip). conv2 mainloop = R12 winner (weight-hoisted
// vertical-strip walk, (img0,img1) fp32x2 pairs).
// smem: sdin64 64KB + conv2 w 144KB + x-pairs 7.2KB + conv1 w 2.3KB + biases.
// =========================================================================
#define CONV2_SMEM (55720 * 4)
__global__ __launch_bounds__(512, 1) void conv12_kernel(
    const float* __restrict__ x,
    const float* __restrict__ w1, const float* __restrict__ b1,
    const float* __restrict__ w2, const float* __restrict__ b2)
{
    extern __shared__ float sm2[];
    u64*   sdin64 = (u64*)sm2;                     // [32 ic][256 pos] (img0,img1)
    u64*   swd64  = (u64*)(sm2 + 16384);           // [ic*9+t][64 ch] (w,w)
    u64*   sx64   = (u64*)(sm2 + 53248);           // [30*30] padded x pairs
    u64*   sw1d   = (u64*)(sm2 + 55048);           // [32 c][9 t] (w,w)
    float* sb1f   = sm2 + 55624;                   // 32
    float* sbf    = sm2 + 55656;                   // 64

    const int pair = blockIdx.x;
    const int img0 = pair * 2, img1 = img0 + 1;
    const int tid  = threadIdx.x;

    // ---- phase 1a: zero + weight staging ----
    for (int i = tid; i < 8192; i += 512) sdin64[i] = 0ull;
    for (int i = tid; i < 900; i += 512) sx64[i] = 0ull;
    for (int idx = tid; idx < 18432; idx += 512) {
        int c = idx & 63, f = idx >> 6;            // f = ic*9 + t
        int ic = f / 9, t = f % 9;
        float v = w2[(c * 32 + ic) * 9 + t];
        swd64[f * 64 + c] = pack2(v, v);
    }
    for (int idx = tid; idx < 288; idx += 512) {
        float v = w1[idx];
        sw1d[idx] = pack2(v, v);
    }
    if (tid < 32) sb1f[tid] = b1[tid];
    if (tid < 64) sbf[tid] = b2[tid];
    __syncthreads();

    // ---- phase 1b: stage raw input pairs (zero-padded 30x30) ----
    for (int i = tid; i < 784; i += 512) {
        int y = i / 28, xx = i % 28;
        sx64[(y + 1) * 30 + xx + 1] = pack2(x[img0 * 784 + i], x[img1 * 784 + i]);
    }
    __syncthreads();

    // ---- phase 2: conv1 (1->32, 3x3) + relu + maxpool2 into sdin64 ----
    for (int item = tid; item < 32 * 196; item += 512) {
        const int c = item / 196, p = item % 196;
        const int oy = p / 14, ox = p % 14;
        u64 wv1[9];
        #pragma unroll
        for (int t = 0; t < 9; t++) wv1[t] = sw1d[c * 9 + t];
        const float bv = sb1f[c];

        u64 patch[4][4];
        #pragma unroll
        for (int r = 0; r < 4; r++)
            #pragma unroll
            for (int cc = 0; cc < 4; cc++)
                patch[r][cc] = sx64[(2 * oy + r) * 30 + 2 * ox + cc];

        u64 acc[4];
        #pragma unroll
        for (int q = 0; q < 4; q++) acc[q] = 0ull;
        #pragma unroll
        for (int ky = 0; ky < 3; ky++) {
            #pragma unroll
            for (int kx = 0; kx < 3; kx++) {
                u64 wt = wv1[ky * 3 + kx];
                acc[0] = ffma2(patch[ky][kx],         wt, acc[0]);
                acc[1] = ffma2(patch[ky][kx + 1],     wt, acc[1]);
                acc[2] = ffma2(patch[ky + 1][kx],     wt, acc[2]);
                acc[3] = ffma2(patch[ky + 1][kx + 1], wt, acc[3]);
            }
        }
        float a0[4], a1[4];
        #pragma unroll
        for (int q = 0; q < 4; q++) unpack2(acc[q], a0[q], a1[q]);
        float m0 = fmaxf(fmaxf(fmaxf(a0[0], a0[1]), fmaxf(a0[2], a0[3])) + bv, 0.f);
        float m1 = fmaxf(fmaxf(fmaxf(a1[0], a1[1]), fmaxf(a1[2], a1[3])) + bv, 0.f);
        sdin64[c * 256 + (oy + 1) * 16 + ox + 1] = pack2(m0, m1);
    }
    __syncthreads();

    // ---- phase 3: conv2 mainloop (R12 winner, unchanged) ----
    const int wd   = tid >> 5;          // 0..15 (warps 14,15 idle)
    const int lane = tid & 31;
    if (wd < 14) {
        const int slot = wd % 7;        // ox column
        const int half = wd / 7;
        const int c    = half * 32 + lane;
        const float bv = sbf[c];
        const int ix   = 2 * slot;

        u64 acc[7][4];
        #pragma unroll
        for (int s = 0; s < 7; s++)
            #pragma unroll
            for (int p = 0; p < 4; p++) acc[s][p] = 0ull;

        for (int ic = 0; ic < 32; ic++) {
            const u64* base = sdin64 + ic * 256;

            u64 wv[9];
            #pragma unroll
            for (int t = 0; t < 9; t++)
                wv[t] = swd64[(ic * 9 + t) * 64 + c];

            u64 pa[4][4];
            #pragma unroll
            for (int r = 0; r < 4; r++) {
                ulonglong2 q0 = *(const ulonglong2*)(base + r * 16 + ix);
                ulonglong2 q1 = *(const ulonglong2*)(base + r * 16 + ix + 2);
                pa[r][0] = q0.x; pa[r][1] = q0.y;
                pa[r][2] = q1.x; pa[r][3] = q1.y;
            }

            #pragma unroll
            for (int s = 0; s < 7; s++) {
                #pragma unroll
                for (int ky = 0; ky < 3; ky++) {
                    #pragma unroll
                    for (int kx = 0; kx < 3; kx++) {
                        u64 wt = wv[ky * 3 + kx];
                        acc[s][0] = ffma2(pa[ky][kx],         wt, acc[s][0]);
                        acc[s][1] = ffma2(pa[ky][kx + 1],     wt, acc[s][1]);
                        acc[s][2] = ffma2(pa[ky + 1][kx],     wt, acc[s][2]);
                        acc[s][3] = ffma2(pa[ky + 1][kx + 1], wt, acc[s][3]);
                    }
                }
                if (s < 6) {
                    #pragma unroll
                    for (int cc = 0; cc < 4; cc++) {
                        pa[0][cc] = pa[2][cc];
                        pa[1][cc] = pa[3][cc];
                    }
                    const int r2 = 2 * s + 4;
                    ulonglong2 q0 = *(const ulonglong2*)(base + r2 * 16 + ix);
                    ulonglong2 q1 = *(const ulonglong2*)(base + r2 * 16 + ix + 2);
                    ulonglong2 q2 = *(const ulonglong2*)(base + (r2 + 1) * 16 + ix);
                    ulonglong2 q3 = *(const ulonglong2*)(base + (r2 + 1) * 16 + ix + 2);
                    pa[2][0] = q0.x; pa[2][1] = q0.y; pa[2][2] = q1.x; pa[2][3] = q1.y;
                    pa[3][0] = q2.x; pa[3][1] = q2.y; pa[3][2] = q3.x; pa[3][3] = q3.y;
                }
            }
        }

        #pragma unroll
        for (int s = 0; s < 7; s++) {
            const int pos = 7 * s + slot;
            float a0[4], a1[4];
            #pragma unroll
            for (int p = 0; p < 4; p++) unpack2(acc[s][p], a0[p], a1[p]);
            float m0 = fmaxf(fmaxf(a0[0], a0[1]), fmaxf(a0[2], a0[3])) + bv;
            float m1 = fmaxf(fmaxf(a1[0], a1[1]), fmaxf(a1[2], a1[3])) + bv;
            g_h2[img0 * 3136 + c * 49 + pos] = fmaxf(m0, 0.f);
            g_h2[img1 * 3136 + c * 49 + pos] = fmaxf(m1, 0.f);
        }
    }
}

// =========================================================================
// Kernel 3: fc, weight-stationary. 64 blocks x 8 images. float4 staging.
// =========================================================================
#define FC_CHUNK 392
#define FC_WPAD  66
#define FC_SMEM  ((8 * 3136 + FC_CHUNK * FC_WPAD) * 4)
__global__ __launch_bounds__(256) void fc_kernel(
    const float* __restrict__ fcw, const float* __restrict__ fcb)
{
    extern __shared__ float smf[];
    float* sact = smf;                  // [8][3136]
    float* swc  = smf + 8 * 3136;       // [392][66] transposed chunk

    const int tid  = threadIdx.x;
    const int img0 = blockIdx.x * 8;

    for (int idx = tid; idx < 8 * 784; idx += 256)
        ((float4*)sact)[idx] = ((const float4*)g_h2)[img0 * 784 + idx];

    const int o2 = (tid & 31) * 2;
    const int q  = tid >> 5;

    u64 acc[8];
    #pragma unroll
    for (int im = 0; im < 8; im++) acc[im] = 0ull;

    const float4* fcw4 = (const float4*)fcw;     // rows of 784 float4

    for (int ch = 0; ch < 8; ch++) {
        __syncthreads();
        for (int idx = tid; idx < 64 * 98; idx += 256) {
            int o = idx / 98, i4 = idx % 98;
            float4 v = fcw4[(size_t)o * 784 + ch * 98 + i4];
            int ib = i4 * 4;
            swc[(ib + 0) * FC_WPAD + o] = v.x;
            swc[(ib + 1) * FC_WPAD + o] = v.y;
            swc[(ib + 2) * FC_WPAD + o] = v.z;
            swc[(ib + 3) * FC_WPAD + o] = v.w;
        }
        __syncthreads();

        const int ibase = q * 49;
        #pragma unroll 7
        for (int t = 0; t < 49; t++) {
            int i = ibase + t;
            u64 wv = *(const u64*)(swc + i * FC_WPAD + o2);
            int gi = ch * FC_CHUNK + i;
            #pragma unroll
            for (int im = 0; im < 8; im++) {
                float a = sact[im * 3136 + gi];
                acc[im] = ffma2(pack2(a, a), wv, acc[im]);
            }
        }
    }
    __syncthreads();

    float* sred = swc;
    #pragma unroll
    for (int im = 0; im < 8; im++) {
        float a0, a1;
        unpack2(acc[im], a0, a1);
        sred[q * 512 + im * 64 + o2]     = a0;
        sred[q * 512 + im * 64 + o2 + 1] = a1;
    }
    __syncthreads();
    for (int idx = tid; idx < 512; idx += 256) {
        int im = idx >> 6, o = idx & 63;
        float s = 0.f;
        #pragma unroll
        for (int qq = 0; qq < 8; qq++) s += sred[qq * 512 + idx];
        g_feat[(img0 + im) * 64 + o] = fmaxf(s + fcb[o], 0.f);
    }
}

// =========================================================================
// Kernel 4: Eq3to3 + relu + mean(ijk).  (R14 winner, unchanged)
// =========================================================================
#define EQ_NT 320
#define EQ_SMEM ((2304 + 64 + 3*4352 + 2*2048 + 64 + 640) * 4)
__global__ __launch_bounds__(EQ_NT, 2) void eq_kernel(
    const float* __restrict__ eqw, const float* __restrict__ eqb)
{
    extern __shared__ float sm[];
    float* sat  = sm;            // [d][k] pad 36 : 2304
    float* sAb  = sat + 2304;    // 64
    float* sV   = sAb + 64;      // [d][e] pad 68 : 4352
    float* sCk  = sV  + 4352;
    float* sCj  = sCk + 4352;
    float* sgk  = sCj + 4352;    // [k][e] : 2048
    float* sgj  = sgk + 2048;    // [j][e] : 2048
    float* ssb  = sgj + 2048;    // 64
    float* sred = ssb + 64;      // [10 warps][64] (also ssb partials temp)

    const int b   = blockIdx.x >> 5;
    const int ii  = blockIdx.x & 31;
    const int tid = threadIdx.x;

    const float* fb = g_feat + b * KK * HID;
    for (int idx = tid; idx < 2048; idx += EQ_NT) {
        int k = idx >> 6, d = idx & 63;
        sat[d * 36 + k] = fb[idx];
    }
    __syncthreads();
    if (tid < 64) {
        const float* row = sat + tid * 36;
        float s = 0.f;
        #pragma unroll
        for (int k = 0; k < 32; k++) s += row[k];
        sAb[tid] = s * (1.0f / 32.0f);
    }
    __syncthreads();

    for (int idx = tid; idx < 4096; idx += EQ_NT) {
        int d = idx >> 6, e = idx & 63;
        const float4* wp = (const float4*)(eqw + (size_t)idx * 8);
        float4 wA = wp[0];   // w0 w1 w2 w3
        float4 wB = wp[1];   // w4 w5 w6 w7
        float ai = sat[d * 36 + ii], ab = sAb[d];
        sV [d * 68 + e] = wA.x * ai + wA.y * ab;
        sCk[d * 68 + e] = ab * (wA.z * ai + wB.x * ab);
        sCj[d * 68 + e] = ab * (wA.w * ai + wB.y * ab);
    }
    if (tid < 256) {
        const int e  = tid & 63;
        const int dq = tid >> 6;        // 0..3, 16 d each
        float s = 0.f;
        #pragma unroll 4
        for (int d = dq * 16; d < dq * 16 + 16; d++) {
            float ab = sAb[d];
            float2 w67 = *(const float2*)(eqw + ((size_t)(d * 64 + e)) * 8 + 6);
            s += ab * ab * (w67.x * sat[d * 36 + ii] + w67.y * ab);
        }
        sred[dq * 64 + e] = s;
    }
    __syncthreads();

    if (tid < 64)
        ssb[tid] = sred[tid] + sred[64 + tid] + sred[128 + tid]
                 + sred[192 + tid] + eqb[tid];
    for (int idx = tid; idx < 2048; idx += EQ_NT) {
        int k = idx >> 6, e = idx & 63;
        float s1 = 0.f, s2 = 0.f;
        #pragma unroll 8
        for (int d = 0; d < 64; d++) {
            float ak = sat[d * 36 + k];
            s1 += sCk[d * 68 + e] * ak;
            s2 += sCj[d * 68 + e] * ak;
        }
        sgk[k * 64 + e] = s1;
        sgj[k * 64 + e] = s2;
    }
    __syncthreads();

    const int w    = tid >> 5;
    const int lane = tid & 31;

    const u64 JT = 0x3221110000ull;
    const u64 KT = 0x3323213210ull;
    const int jt = (int)((JT >> (4 * w)) & 15);
    const int kt = (int)((KT >> (4 * w)) & 15);
    const int j0 = jt * 8;
    const int k0 = kt * 8;
    const bool diag = (jt == kt);

    float esum0 = 0.f, esum1 = 0.f;

    #pragma unroll
    for (int pass = 0; pass < 2; pass++) {
        const int e = lane + 32 * pass;

        u64 acc[8][4];
        #pragma unroll
        for (int jj = 0; jj < 8; jj++)
            #pragma unroll
            for (int kp = 0; kp < 4; kp++) acc[jj][kp] = 0ull;

        for (int d = 0; d < 64; d++) {
            const float* rd = sat + d * 36;
            float vl = sV[d * 68 + e];
            float4 ajA = *(const float4*)(rd + j0);
            float4 ajB = *(const float4*)(rd + j0 + 4);
            ulonglong2 akA = *(const ulonglong2*)(rd + k0);
            ulonglong2 akB = *(const ulonglong2*)(rd + k0 + 4);
            float aj[8] = {ajA.x, ajA.y, ajA.z, ajA.w, ajB.x, ajB.y, ajB.z, ajB.w};
            u64 ak[4] = {akA.x, akA.y, akB.x, akB.y};

            #pragma unroll
            for (int jj = 0; jj < 8; jj++) {
                float tv = aj[jj] * vl;
                u64 tp = pack2(tv, tv);
                acc[jj][0] = ffma2(tp, ak[0], acc[jj][0]);
                acc[jj][1] = ffma2(tp, ak[1], acc[jj][1]);
                acc[jj][2] = ffma2(tp, ak[2], acc[jj][2]);
                acc[jj][3] = ffma2(tp, ak[3], acc[jj][3]);
            }
        }

        const float sbv = ssb[e];
        float gkk[8], gjk[8];
        #pragma unroll
        for (int u = 0; u < 8; u++) {
            gkk[u] = sgk[(k0 + u) * 64 + e];
            gjk[u] = sgj[(k0 + u) * 64 + e];
        }
        float es = 0.f;
        #pragma unroll
        for (int jj = 0; jj < 8; jj++) {
            const int j = j0 + jj;
            const float gjj = sgj[j * 64 + e];
            const float gkj = sgk[j * 64 + e];
            #pragma unroll
            for (int kp = 0; kp < 4; kp++) {
                float a0, a1;
                unpack2(acc[jj][kp], a0, a1);
                const int ua = 2 * kp, ub = ua + 1;
                const int ka = k0 + ua, kb = k0 + ub;
                float p0 = a0 + gjj + gkk[ua] + sbv;
                float q0 = a0 + gjk[ua] + gkj + sbv;
                float p1 = a1 + gjj + gkk[ub] + sbv;
                float q1 = a1 + gjk[ub] + gkj + sbv;
                if (!diag || ka >= j) es += fmaxf(p0, 0.f);
                if (!diag || ka >  j) es += fmaxf(q0, 0.f);
                if (!diag || kb >= j) es += fmaxf(p1, 0.f);
                if (!diag || kb >  j) es += fmaxf(q1, 0.f);
            }
        }
        if (pass == 0) esum0 = es; else esum1 = es;
    }

    sred[w * 64 + lane]      = esum0;
    sred[w * 64 + lane + 32] = esum1;
    __syncthreads();
    if (tid < 64) {
        float s = 0.f;
        #pragma unroll
        for (int g = 0; g < 10; g++) s += sred[g * 64 + tid];
        g_part[blockIdx.x * 64 + tid] = s;
    }
}

// =========================================================================
// Kernel 5: final
// =========================================================================
__global__ __launch_bounds__(64) void final_kernel(
    const float* __restrict__ outw, const float* __restrict__ outb,
    float* __restrict__ out)
{
    __shared__ float red[64];
    const int b = blockIdx.x, e = threadIdx.x;
    float s = 0.f;
    #pragma unroll
    for (int i = 0; i < 32; i++) s += g_part[(b * 32 + i) * 64 + e];
    float x8 = s * (1.0f / 32768.0f);
    red[e] = fmaxf(x8, 0.f) * outw[e];
    __syncthreads();
    #pragma unroll
    for (int off = 32; off; off >>= 1) {
        if (e < off) red[e] += red[e + off];
        __syncthreads();
    }
    if (e == 0) out[b] = red[0] + outb[0];
}

// =========================================================================
extern "C" void kernel_launch(void* const* d_in, const int* in_sizes, int n_in,
                              void* d_out, int out_size)
{
    const float* x    = (const float*)d_in[0];
    const float* c1w  = (const float*)d_in[1];
    const float* c1b  = (const float*)d_in[2];
    const float* c2w  = (const float*)d_in[3];
    const float* c2b  = (const float*)d_in[4];
    const float* fcw  = (const float*)d_in[5];
    const float* fcb  = (const float*)d_in[6];
    const float* eqw  = (const float*)d_in[7];
    const float* eqb  = (const float*)d_in[8];
    const float* outw = (const float*)d_in[9];
    const float* outb = (const float*)d_in[10];
    float* out = (float*)d_out;

    cudaFuncSetAttribute(conv12_kernel, cudaFuncAttributeMaxDynamicSharedMemorySize, CONV2_SMEM);
    cudaFuncSetAttribute(fc_kernel,     cudaFuncAttributeMaxDynamicSharedMemorySize, FC_SMEM);
    cudaFuncSetAttribute(eq_kernel,     cudaFuncAttributeMaxDynamicSharedMemorySize, EQ_SMEM);

    conv12_kernel<<<NIMG / 2, 512, CONV2_SMEM>>>(x, c1w, c1b, c2w, c2b);
    fc_kernel<<<64, 256, FC_SMEM>>>(fcw, fcb);
    eq_kernel<<<NIMG, EQ_NT, EQ_SMEM>>>(eqw, eqb);
    final_kernel<<<BB, 64>>>(outw, outb, out);
}